// round 11
// baseline (speedup 1.0000x reference)
#include <cuda_runtime.h>
#include <cuda_fp16.h>
#include <cstdint>

#define BDIM 4
#define TDIM 2048
#define CDIM 768
#define HDIM 12
#define DDIM 64
#define C3   2304
#define MROWS (BDIM * TDIM)

// fp16 scratch
__device__ __half g_xh[MROWS * CDIM];
__device__ __half g_wqkv[CDIM * C3];
__device__ __half g_wproj[CDIM * CDIM];
__device__ __half g_qkv[MROWS * C3];      // Q pre-scaled by 0.125
__device__ __half g_y[MROWS * CDIM];

// ---------------------------------------------------------------------------
// helpers
// ---------------------------------------------------------------------------
__device__ __forceinline__ unsigned f2h2(float lo, float hi) {
    unsigned r;
    asm("cvt.rn.f16x2.f32 %0, %1, %2;" : "=r"(r) : "f"(hi), "f"(lo));
    return r;
}
__device__ __forceinline__ void mma16816(float d[4], const unsigned a[4], const unsigned b[2]) {
    asm volatile(
        "mma.sync.aligned.m16n8k16.row.col.f32.f16.f16.f32 "
        "{%0,%1,%2,%3}, {%4,%5,%6,%7}, {%8,%9}, {%0,%1,%2,%3};\n"
        : "+f"(d[0]), "+f"(d[1]), "+f"(d[2]), "+f"(d[3])
        : "r"(a[0]), "r"(a[1]), "r"(a[2]), "r"(a[3]), "r"(b[0]), "r"(b[1]));
}
__device__ __forceinline__ void cp16(uint32_t dst, const void* src) {
    asm volatile("cp.async.cg.shared.global [%0], [%1], 16;" :: "r"(dst), "l"(src));
}
__device__ __forceinline__ void cp_commit() { asm volatile("cp.async.commit_group;"); }
__device__ __forceinline__ void cp_wait1() { asm volatile("cp.async.wait_group 1;"); }
__device__ __forceinline__ void cp_wait0() { asm volatile("cp.async.wait_group 0;"); }

__device__ __forceinline__ void ldsm4(unsigned& r0, unsigned& r1, unsigned& r2, unsigned& r3,
                                      uint32_t addr) {
    asm volatile("ldmatrix.sync.aligned.m8n8.x4.shared.b16 {%0,%1,%2,%3}, [%4];"
                 : "=r"(r0), "=r"(r1), "=r"(r2), "=r"(r3) : "r"(addr));
}
__device__ __forceinline__ void ldsm4t(unsigned& r0, unsigned& r1, unsigned& r2, unsigned& r3,
                                       uint32_t addr) {
    asm volatile("ldmatrix.sync.aligned.m8n8.x4.trans.shared.b16 {%0,%1,%2,%3}, [%4];"
                 : "=r"(r0), "=r"(r1), "=r"(r2), "=r"(r3) : "r"(addr));
}

// ---------------------------------------------------------------------------
// fp32 -> fp16 convert
// ---------------------------------------------------------------------------
__global__ void f2h_kernel(const float* __restrict__ in, __half* __restrict__ out, int n)
{
    int i = (blockIdx.x * blockDim.x + threadIdx.x) * 4;
    if (i < n) {
        float4 v = *(const float4*)(in + i);
        __half2* o = (__half2*)(out + i);
        o[0] = __floats2half2_rn(v.x, v.y);
        o[1] = __floats2half2_rn(v.z, v.w);
    }
}

// ---------------------------------------------------------------------------
// fp16 GEMM: out[M,N] = A[M,K] @ W[K,N] + bias.  Block 128x256, BK=64,
// 256 thr = 8 warps of 64x64.  3-stage cp.async, 1 barrier/iter, ldmatrix.
// smem/stage: A 128x64h (128B rows, XOR-swz) @0 ... B 64x256h (512B rows) @16K.
// ---------------------------------------------------------------------------
#define GSTAGE 49152
#define GS_BYTES (3 * GSTAGE)

template<typename OutT, int QSCALE>
__global__ __launch_bounds__(256, 1)
void gemm_h(const __half* __restrict__ A, const __half* __restrict__ W,
            const float* __restrict__ bias, OutT* __restrict__ out,
            int M, int N, int K)
{
    extern __shared__ __align__(16) char gsmc[];
    const uint32_t sbase = (uint32_t)__cvta_generic_to_shared(gsmc);

    const int tid  = threadIdx.x;
    const int lane = tid & 31, wid = tid >> 5;
    const int g = lane >> 2, t = lane & 3;
    const int wm = (wid & 1) * 64;          // warp m-offset (2 m-warps)
    const int wn = (wid >> 1) * 64;         // warp n-offset (4 n-warps)
    const int m0 = blockIdx.y * 128, n0 = blockIdx.x * 256;

    // staging: A row ar (128B, 2 thr/row x 4 segs); B row br (512B, 4 thr/row x 8 segs)
    const int ar = tid >> 1, as0 = (tid & 1) * 4;
    const int br = tid >> 2, bs0 = (tid & 3) * 8;
    const __half* Ap = A + (size_t)(m0 + ar) * K + as0 * 8;
    const __half* Wp = W + (size_t)br * N + n0 + bs0 * 8;

    auto stageg = [&](int it) {
        const uint32_t ab = sbase + (uint32_t)(it % 3) * GSTAGE;
        const uint32_t bb = ab + 16384;
        const __half* ap = Ap + it * 64;
        const __half* wp = Wp + (size_t)it * 64 * N;
        #pragma unroll
        for (int s = 0; s < 4; s++) {
            int seg = as0 + s;
            cp16(ab + (uint32_t)(ar * 128 + ((seg ^ (ar & 7)) << 4)), ap + s * 8);
        }
        #pragma unroll
        for (int s = 0; s < 8; s++) {
            int seg = bs0 + s;
            cp16(bb + (uint32_t)(br * 512 + ((seg ^ (br & 7)) << 4)), wp + s * 8);
        }
        cp_commit();
    };

    float acc[4][8][4] = {};

    const int NK = K / 64;
    stageg(0);
    stageg(1);

    for (int it = 0; it < NK; it++) {
        if (it < NK - 1) cp_wait1(); else cp_wait0();
        __syncthreads();
        if (it + 2 < NK) stageg(it + 2);

        const uint32_t ab = sbase + (uint32_t)(it % 3) * GSTAGE;
        const uint32_t bb = ab + 16384;

        #pragma unroll
        for (int kc = 0; kc < 4; kc++) {
            unsigned af[4][4];
            #pragma unroll
            for (int mi = 0; mi < 4; mi++) {
                int row = wm + mi * 16 + (lane & 15);
                int sg  = kc * 2 + (lane >> 4);
                ldsm4(af[mi][0], af[mi][1], af[mi][2], af[mi][3],
                      ab + (uint32_t)(row * 128 + ((sg ^ (row & 7)) << 4)));
            }
            unsigned bf[8][2];
            #pragma unroll
            for (int np = 0; np < 4; np++) {
                int row = kc * 16 + ((lane >> 3) & 1) * 8 + (lane & 7);
                int sg  = (wn >> 3) + 2 * np + (lane >> 4);
                unsigned b0, b1, b2, b3;
                ldsm4t(b0, b1, b2, b3,
                       bb + (uint32_t)(row * 512 + ((sg ^ (row & 7)) << 4)));
                bf[2 * np][0] = b0;     bf[2 * np][1] = b1;
                bf[2 * np + 1][0] = b2; bf[2 * np + 1][1] = b3;
            }
            #pragma unroll
            for (int mi = 0; mi < 4; mi++)
                #pragma unroll
                for (int ni = 0; ni < 8; ni++)
                    mma16816(acc[mi][ni], af[mi], bf[ni]);
        }
    }

    #pragma unroll
    for (int mi = 0; mi < 4; mi++) {
        #pragma unroll
        for (int ni = 0; ni < 8; ni++) {
            int r = m0 + wm + mi * 16 + g;
            int c = n0 + wn + ni * 8 + 2 * t;
            float b0 = bias[c], b1 = bias[c + 1];
            float v0 = acc[mi][ni][0] + b0, v1 = acc[mi][ni][1] + b1;
            float v2 = acc[mi][ni][2] + b0, v3 = acc[mi][ni][3] + b1;
            if (QSCALE && c < CDIM) {
                v0 *= 0.125f; v1 *= 0.125f; v2 *= 0.125f; v3 *= 0.125f;
            }
            if constexpr (sizeof(OutT) == 2) {
                __half* o = (__half*)out;
                *(__half2*)(o + (size_t)r * N + c) = __floats2half2_rn(v0, v1);
                *(__half2*)(o + (size_t)(r + 8) * N + c) = __floats2half2_rn(v2, v3);
            } else {
                float* o = (float*)out;
                *(float2*)(o + (size_t)r * N + c) = make_float2(v0, v1);
                *(float2*)(o + (size_t)(r + 8) * N + c) = make_float2(v2, v3);
            }
        }
    }
}

// ---------------------------------------------------------------------------
// Flash attention fp16 (unchanged from round 10).
// ---------------------------------------------------------------------------
#define FTILE 8192

extern __shared__ __align__(16) char fa_smc[];

__global__ __launch_bounds__(256, 2)
void flash_f16(const __half* __restrict__ qh, __half* __restrict__ y)
{
    const int tid  = threadIdx.x;
    const int lane = tid & 31, wid = tid >> 5;
    const int g = lane >> 2, t = lane & 3;
    const int r0 = wid * 16;
    const int itile = blockIdx.x, h = blockIdx.y, b = blockIdx.z;
    const int q0 = itile * 128;
    const size_t base = (size_t)b * TDIM * C3;

    const uint32_t sbase = (uint32_t)__cvta_generic_to_shared(fa_smc);

    const int sc = tid >> 2, ss0 = (tid & 3) * 2;
    const __half* kv_src = qh + base + (size_t)sc * C3 + CDIM + h * DDIM;

    unsigned Qf[4][4];
    {
        const __half* q0p = qh + base + (size_t)(q0 + r0 + g) * C3 + h * DDIM;
        const __half* q1p = q0p + 8 * C3;
        #pragma unroll
        for (int ds = 0; ds < 4; ds++) {
            Qf[ds][0] = *(const unsigned*)(q0p + ds * 16 + 2 * t);
            Qf[ds][1] = *(const unsigned*)(q1p + ds * 16 + 2 * t);
            Qf[ds][2] = *(const unsigned*)(q0p + ds * 16 + 2 * t + 8);
            Qf[ds][3] = *(const unsigned*)(q1p + ds * 16 + 2 * t + 8);
        }
    }

    float O[8][4] = {};
    float mrow[2] = {-1e30f, -1e30f};
    float lrow[2] = {0.f, 0.f};

    const int nkt = 2 * (itile + 1);

    auto stage = [&](int jt) {
        const int bi = jt % 3;
        const __half* src = kv_src + (size_t)(jt * 64) * C3;
        const uint32_t krow = sbase + (uint32_t)bi * FTILE + sc * 128;
        const uint32_t vrow = krow + 3 * FTILE;
        #pragma unroll
        for (int si = 0; si < 2; si++) {
            int s = ss0 + si;
            uint32_t off = (uint32_t)((s ^ (sc & 7)) << 4);
            cp16(krow + off, src + s * 8);
            cp16(vrow + off, src + CDIM + s * 8);
        }
        cp_commit();
    };

    stage(0);
    stage(1);

    for (int jt = 0; jt < nkt; jt++) {
        const int k0 = jt * 64;
        if (jt < nkt - 1) cp_wait1(); else cp_wait0();
        __syncthreads();
        if (jt + 2 < nkt) stage(jt + 2);

        const int bi = jt % 3;
        const uint32_t kb = sbase + (uint32_t)bi * FTILE;
        const uint32_t vb = kb + 3 * FTILE;

        const bool active = (k0 <= q0 + r0 + 15);
        if (active) {
            float S[8][4] = {};
            #pragma unroll
            for (int ni = 0; ni < 8; ni++) {
                unsigned bk[4][2];
                #pragma unroll
                for (int p = 0; p < 2; p++) {
                    int c  = ni * 8 + (lane & 7);
                    int sg = 4 * p + (lane >> 3);
                    uint32_t addr = kb + (uint32_t)(c * 128 + ((sg ^ (c & 7)) << 4));
                    ldsm4(bk[2 * p][0], bk[2 * p][1], bk[2 * p + 1][0], bk[2 * p + 1][1], addr);
                }
                #pragma unroll
                for (int ds = 0; ds < 4; ds++)
                    mma16816(S[ni], Qf[ds], bk[ds]);
            }

            const int rg0 = q0 + r0 + g, rg1 = rg0 + 8;
            if (k0 + 63 > q0 + r0) {
                #pragma unroll
                for (int ni = 0; ni < 8; ni++) {
                    int c0 = k0 + ni * 8 + 2 * t;
                    if (c0 > rg0)     S[ni][0] = -1e30f;
                    if (c0 + 1 > rg0) S[ni][1] = -1e30f;
                    if (c0 > rg1)     S[ni][2] = -1e30f;
                    if (c0 + 1 > rg1) S[ni][3] = -1e30f;
                }
            }

            float mx0 = -1e30f, mx1 = -1e30f;
            #pragma unroll
            for (int ni = 0; ni < 8; ni++) {
                mx0 = fmaxf(mx0, fmaxf(S[ni][0], S[ni][1]));
                mx1 = fmaxf(mx1, fmaxf(S[ni][2], S[ni][3]));
            }
            mx0 = fmaxf(mx0, __shfl_xor_sync(0xffffffffu, mx0, 1));
            mx0 = fmaxf(mx0, __shfl_xor_sync(0xffffffffu, mx0, 2));
            mx1 = fmaxf(mx1, __shfl_xor_sync(0xffffffffu, mx1, 1));
            mx1 = fmaxf(mx1, __shfl_xor_sync(0xffffffffu, mx1, 2));

            float mn0 = fmaxf(mrow[0], mx0), mn1 = fmaxf(mrow[1], mx1);
            float a0 = __expf(mrow[0] - mn0), a1 = __expf(mrow[1] - mn1);
            mrow[0] = mn0; mrow[1] = mn1;

            float s0 = 0.f, s1 = 0.f;
            #pragma unroll
            for (int ni = 0; ni < 8; ni++) {
                S[ni][0] = __expf(S[ni][0] - mn0);
                S[ni][1] = __expf(S[ni][1] - mn0);
                S[ni][2] = __expf(S[ni][2] - mn1);
                S[ni][3] = __expf(S[ni][3] - mn1);
                s0 += S[ni][0] + S[ni][1];
                s1 += S[ni][2] + S[ni][3];
            }
            s0 += __shfl_xor_sync(0xffffffffu, s0, 1);
            s0 += __shfl_xor_sync(0xffffffffu, s0, 2);
            s1 += __shfl_xor_sync(0xffffffffu, s1, 1);
            s1 += __shfl_xor_sync(0xffffffffu, s1, 2);
            lrow[0] = lrow[0] * a0 + s0;
            lrow[1] = lrow[1] * a1 + s1;

            #pragma unroll
            for (int di = 0; di < 8; di++) {
                O[di][0] *= a0; O[di][1] *= a0;
                O[di][2] *= a1; O[di][3] *= a1;
            }

            #pragma unroll
            for (int cs = 0; cs < 4; cs++) {
                unsigned ap[4];
                ap[0] = f2h2(S[2 * cs][0],     S[2 * cs][1]);
                ap[1] = f2h2(S[2 * cs][2],     S[2 * cs][3]);
                ap[2] = f2h2(S[2 * cs + 1][0], S[2 * cs + 1][1]);
                ap[3] = f2h2(S[2 * cs + 1][2], S[2 * cs + 1][3]);
                #pragma unroll
                for (int dp = 0; dp < 4; dp++) {
                    int row = cs * 16 + ((lane >> 3) & 1) * 8 + (lane & 7);
                    int sg  = 2 * dp + (lane >> 4);
                    uint32_t addr = vb + (uint32_t)(row * 128 + ((sg ^ (row & 7)) << 4));
                    unsigned bv[4];
                    ldsm4t(bv[0], bv[1], bv[2], bv[3], addr);
                    mma16816(O[2 * dp],     ap, bv);
                    mma16816(O[2 * dp + 1], ap, bv + 2);
                }
            }
        }
    }

    float inv0 = 1.f / lrow[0], inv1 = 1.f / lrow[1];
    int rg0 = q0 + r0 + g, rg1 = rg0 + 8;
    #pragma unroll
    for (int di = 0; di < 8; di++) {
        int c = h * DDIM + di * 8 + 2 * t;
        *(__half2*)(y + ((size_t)b * TDIM + rg0) * CDIM + c) =
            __floats2half2_rn(O[di][0] * inv0, O[di][1] * inv0);
        *(__half2*)(y + ((size_t)b * TDIM + rg1) * CDIM + c) =
            __floats2half2_rn(O[di][2] * inv1, O[di][3] * inv1);
    }
}

// ---------------------------------------------------------------------------
extern "C" void kernel_launch(void* const* d_in, const int* in_sizes, int n_in,
                              void* d_out, int out_size)
{
    const float* x     = (const float*)d_in[0];
    const float* Wqkv  = (const float*)d_in[1];
    const float* bqkv  = (const float*)d_in[2];
    const float* Wproj = (const float*)d_in[3];
    const float* bproj = (const float*)d_in[4];
    float* out = (float*)d_out;

    __half *xh, *wqkv, *wproj, *qkv, *yb;
    cudaGetSymbolAddress((void**)&xh, g_xh);
    cudaGetSymbolAddress((void**)&wqkv, g_wqkv);
    cudaGetSymbolAddress((void**)&wproj, g_wproj);
    cudaGetSymbolAddress((void**)&qkv, g_qkv);
    cudaGetSymbolAddress((void**)&yb, g_y);

    f2h_kernel<<<(MROWS * CDIM / 4 + 255) / 256, 256>>>(x, xh, MROWS * CDIM);
    f2h_kernel<<<(CDIM * C3 / 4 + 255) / 256, 256>>>(Wqkv, wqkv, CDIM * C3);
    f2h_kernel<<<(CDIM * CDIM / 4 + 255) / 256, 256>>>(Wproj, wproj, CDIM * CDIM);

    cudaFuncSetAttribute(gemm_h<__half, 1>, cudaFuncAttributeMaxDynamicSharedMemorySize, GS_BYTES);
    cudaFuncSetAttribute(gemm_h<float, 0>,  cudaFuncAttributeMaxDynamicSharedMemorySize, GS_BYTES);

    // 1) QKV projection -> fp16 (Q cols scaled by 0.125)
    gemm_h<__half, 1><<<dim3(C3 / 256, MROWS / 128), 256, GS_BYTES>>>(
        xh, wqkv, bqkv, qkv, MROWS, C3, CDIM);

    // 2) Causal flash attention
    size_t fsm = 6 * FTILE;
    cudaFuncSetAttribute(flash_f16, cudaFuncAttributeMaxDynamicSharedMemorySize, (int)fsm);
    flash_f16<<<dim3(TDIM / 128, HDIM, BDIM), 256, fsm>>>(qkv, yb);

    // 3) Output projection -> fp32
    gemm_h<float, 0><<<dim3(CDIM / 256, MROWS / 128), 256, GS_BYTES>>>(
        yb, wproj, bproj, out, MROWS, CDIM, CDIM);
}

// round 16
// speedup vs baseline: 1.2227x; 1.2227x over previous
#include <cuda_runtime.h>
#include <cuda_fp16.h>
#include <cstdint>

#define BDIM 4
#define TDIM 2048
#define CDIM 768
#define HDIM 12
#define DDIM 64
#define C3   2304
#define MROWS (BDIM * TDIM)

// fp16 scratch
__device__ __half g_xh[MROWS * CDIM];
__device__ __half g_wqkv[CDIM * C3];
__device__ __half g_wproj[CDIM * CDIM];
__device__ __half g_qkv[MROWS * C3];      // Q pre-scaled by 0.125
__device__ __half g_y[MROWS * CDIM];

// ---------------------------------------------------------------------------
// helpers
// ---------------------------------------------------------------------------
__device__ __forceinline__ unsigned f2h2(float lo, float hi) {
    unsigned r;
    asm("cvt.rn.f16x2.f32 %0, %1, %2;" : "=r"(r) : "f"(hi), "f"(lo));
    return r;
}
__device__ __forceinline__ void mma16816(float d[4], const unsigned a[4], const unsigned b[2]) {
    asm volatile(
        "mma.sync.aligned.m16n8k16.row.col.f32.f16.f16.f32 "
        "{%0,%1,%2,%3}, {%4,%5,%6,%7}, {%8,%9}, {%0,%1,%2,%3};\n"
        : "+f"(d[0]), "+f"(d[1]), "+f"(d[2]), "+f"(d[3])
        : "r"(a[0]), "r"(a[1]), "r"(a[2]), "r"(a[3]), "r"(b[0]), "r"(b[1]));
}
__device__ __forceinline__ void cp16(uint32_t dst, const void* src) {
    asm volatile("cp.async.cg.shared.global [%0], [%1], 16;" :: "r"(dst), "l"(src));
}
__device__ __forceinline__ void cp_commit() { asm volatile("cp.async.commit_group;"); }
__device__ __forceinline__ void cp_wait1() { asm volatile("cp.async.wait_group 1;"); }
__device__ __forceinline__ void cp_wait0() { asm volatile("cp.async.wait_group 0;"); }

__device__ __forceinline__ void ldsm4(unsigned& r0, unsigned& r1, unsigned& r2, unsigned& r3,
                                      uint32_t addr) {
    asm volatile("ldmatrix.sync.aligned.m8n8.x4.shared.b16 {%0,%1,%2,%3}, [%4];"
                 : "=r"(r0), "=r"(r1), "=r"(r2), "=r"(r3) : "r"(addr));
}
__device__ __forceinline__ void ldsm4t(unsigned& r0, unsigned& r1, unsigned& r2, unsigned& r3,
                                       uint32_t addr) {
    asm volatile("ldmatrix.sync.aligned.m8n8.x4.trans.shared.b16 {%0,%1,%2,%3}, [%4];"
                 : "=r"(r0), "=r"(r1), "=r"(r2), "=r"(r3) : "r"(addr));
}

// ---------------------------------------------------------------------------
// fused fp32 -> fp16 convert of x, W_qkv, W_proj in one launch
// ---------------------------------------------------------------------------
#define N_X  (MROWS * CDIM)
#define N_WQ (CDIM * C3)
#define N_WP (CDIM * CDIM)

__global__ void f2h_all(const float* __restrict__ x, const float* __restrict__ wq,
                        const float* __restrict__ wp,
                        __half* __restrict__ xh, __half* __restrict__ wqh,
                        __half* __restrict__ wph)
{
    int i = (blockIdx.x * blockDim.x + threadIdx.x) * 4;
    const float* src;
    __half* dst;
    if (i < N_X) {
        src = x + i; dst = xh + i;
    } else if (i < N_X + N_WQ) {
        src = wq + (i - N_X); dst = wqh + (i - N_X);
    } else if (i < N_X + N_WQ + N_WP) {
        src = wp + (i - N_X - N_WQ); dst = wph + (i - N_X - N_WQ);
    } else {
        return;
    }
    float4 v = *(const float4*)src;
    __half2* o = (__half2*)dst;
    o[0] = __floats2half2_rn(v.x, v.y);
    o[1] = __floats2half2_rn(v.z, v.w);
}

// ---------------------------------------------------------------------------
// fp16 GEMM (round-10 config, single barrier/iter):
// out[M,N] = A[M,K] @ W[K,N] + bias.  Block 128x128, BK=64, 256 thr,
// 8 warps of 64x32, 3-stage cp.async, ldmatrix feeds.
// ---------------------------------------------------------------------------
#define GSTAGE 32768
#define GS_BYTES (3 * GSTAGE)

template<typename OutT, int QSCALE>
__global__ __launch_bounds__(256, 2)
void gemm_h(const __half* __restrict__ A, const __half* __restrict__ W,
            const float* __restrict__ bias, OutT* __restrict__ out,
            int M, int N, int K)
{
    extern __shared__ __align__(16) char gsmc[];
    const uint32_t sbase = (uint32_t)__cvta_generic_to_shared(gsmc);

    const int tid  = threadIdx.x;
    const int lane = tid & 31, wid = tid >> 5;
    const int g = lane >> 2, t = lane & 3;
    const int wm = (wid & 1) * 64;
    const int wn = (wid >> 1) * 32;
    const int m0 = blockIdx.y * 128, n0 = blockIdx.x * 128;

    const int ar = tid >> 1, as0 = (tid & 1) * 4;
    const int br = tid >> 2, bs0 = (tid & 3) * 4;
    const __half* Ap = A + (size_t)(m0 + ar) * K + as0 * 8;
    const __half* Wp = W + (size_t)br * N + n0 + bs0 * 8;

    auto stageg = [&](int it) {
        const uint32_t ab = sbase + (uint32_t)(it % 3) * GSTAGE;
        const uint32_t bb = ab + 16384;
        const __half* ap = Ap + it * 64;
        const __half* wp = Wp + (size_t)it * 64 * N;
        #pragma unroll
        for (int s = 0; s < 4; s++) {
            int seg = as0 + s;
            cp16(ab + (uint32_t)(ar * 128 + ((seg ^ (ar & 7)) << 4)), ap + s * 8);
        }
        #pragma unroll
        for (int s = 0; s < 4; s++) {
            int seg = bs0 + s;
            cp16(bb + (uint32_t)(br * 256 + ((seg ^ (br & 7)) << 4)), wp + s * 8);
        }
        cp_commit();
    };

    float acc[4][4][4] = {};

    const int NK = K / 64;
    stageg(0);
    stageg(1);

    for (int it = 0; it < NK; it++) {
        if (it < NK - 1) cp_wait1(); else cp_wait0();
        __syncthreads();
        if (it + 2 < NK) stageg(it + 2);

        const uint32_t ab = sbase + (uint32_t)(it % 3) * GSTAGE;
        const uint32_t bb = ab + 16384;

        #pragma unroll
        for (int kc = 0; kc < 4; kc++) {
            unsigned af[4][4];
            #pragma unroll
            for (int mi = 0; mi < 4; mi++) {
                int row = wm + mi * 16 + (lane & 15);
                int sg  = kc * 2 + (lane >> 4);
                ldsm4(af[mi][0], af[mi][1], af[mi][2], af[mi][3],
                      ab + (uint32_t)(row * 128 + ((sg ^ (row & 7)) << 4)));
            }
            unsigned bf[4][2];
            #pragma unroll
            for (int np = 0; np < 2; np++) {
                int row = kc * 16 + ((lane >> 3) & 1) * 8 + (lane & 7);
                int sg  = (wn >> 3) + 2 * np + (lane >> 4);
                unsigned b0, b1, b2, b3;
                ldsm4t(b0, b1, b2, b3,
                       bb + (uint32_t)(row * 256 + ((sg ^ (row & 7)) << 4)));
                bf[2 * np][0] = b0; bf[2 * np][1] = b1;
                bf[2 * np + 1][0] = b2; bf[2 * np + 1][1] = b3;
            }
            #pragma unroll
            for (int mi = 0; mi < 4; mi++)
                #pragma unroll
                for (int ni = 0; ni < 4; ni++)
                    mma16816(acc[mi][ni], af[mi], bf[ni]);
        }
    }

    #pragma unroll
    for (int mi = 0; mi < 4; mi++) {
        #pragma unroll
        for (int ni = 0; ni < 4; ni++) {
            int r = m0 + wm + mi * 16 + g;
            int c = n0 + wn + ni * 8 + 2 * t;
            float b0 = bias[c], b1 = bias[c + 1];
            float v0 = acc[mi][ni][0] + b0, v1 = acc[mi][ni][1] + b1;
            float v2 = acc[mi][ni][2] + b0, v3 = acc[mi][ni][3] + b1;
            if (QSCALE && c < CDIM) {
                v0 *= 0.125f; v1 *= 0.125f; v2 *= 0.125f; v3 *= 0.125f;
            }
            if constexpr (sizeof(OutT) == 2) {
                __half* o = (__half*)out;
                *(__half2*)(o + (size_t)r * N + c) = __floats2half2_rn(v0, v1);
                *(__half2*)(o + (size_t)(r + 8) * N + c) = __floats2half2_rn(v2, v3);
            } else {
                float* o = (float*)out;
                *(float2*)(o + (size_t)r * N + c) = make_float2(v0, v1);
                *(float2*)(o + (size_t)(r + 8) * N + c) = make_float2(v2, v3);
            }
        }
    }
}

// ---------------------------------------------------------------------------
// Flash attention fp16 (round-10 structure; heavy q-tiles scheduled first).
// ---------------------------------------------------------------------------
#define FTILE 8192

extern __shared__ __align__(16) char fa_smc[];

__global__ __launch_bounds__(256, 2)
void flash_f16(const __half* __restrict__ qh, __half* __restrict__ y)
{
    const int tid  = threadIdx.x;
    const int lane = tid & 31, wid = tid >> 5;
    const int g = lane >> 2, t = lane & 3;
    const int r0 = wid * 16;
    const int itile = gridDim.x - 1 - blockIdx.x;   // heavy tiles first
    const int h = blockIdx.y, b = blockIdx.z;
    const int q0 = itile * 128;
    const size_t base = (size_t)b * TDIM * C3;

    const uint32_t sbase = (uint32_t)__cvta_generic_to_shared(fa_smc);

    const int sc = tid >> 2, ss0 = (tid & 3) * 2;
    const __half* kv_src = qh + base + (size_t)sc * C3 + CDIM + h * DDIM;

    unsigned Qf[4][4];
    {
        const __half* q0p = qh + base + (size_t)(q0 + r0 + g) * C3 + h * DDIM;
        const __half* q1p = q0p + 8 * C3;
        #pragma unroll
        for (int ds = 0; ds < 4; ds++) {
            Qf[ds][0] = *(const unsigned*)(q0p + ds * 16 + 2 * t);
            Qf[ds][1] = *(const unsigned*)(q1p + ds * 16 + 2 * t);
            Qf[ds][2] = *(const unsigned*)(q0p + ds * 16 + 2 * t + 8);
            Qf[ds][3] = *(const unsigned*)(q1p + ds * 16 + 2 * t + 8);
        }
    }

    float O[8][4] = {};
    float mrow[2] = {-1e30f, -1e30f};
    float lrow[2] = {0.f, 0.f};

    const int nkt = 2 * (itile + 1);

    auto stage = [&](int jt) {
        const int bi = jt % 3;
        const __half* src = kv_src + (size_t)(jt * 64) * C3;
        const uint32_t krow = sbase + (uint32_t)bi * FTILE + sc * 128;
        const uint32_t vrow = krow + 3 * FTILE;
        #pragma unroll
        for (int si = 0; si < 2; si++) {
            int s = ss0 + si;
            uint32_t off = (uint32_t)((s ^ (sc & 7)) << 4);
            cp16(krow + off, src + s * 8);
            cp16(vrow + off, src + CDIM + s * 8);
        }
        cp_commit();
    };

    stage(0);
    stage(1);

    for (int jt = 0; jt < nkt; jt++) {
        const int k0 = jt * 64;
        if (jt < nkt - 1) cp_wait1(); else cp_wait0();
        __syncthreads();
        if (jt + 2 < nkt) stage(jt + 2);

        const int bi = jt % 3;
        const uint32_t kb = sbase + (uint32_t)bi * FTILE;
        const uint32_t vb = kb + 3 * FTILE;

        const bool active = (k0 <= q0 + r0 + 15);
        if (active) {
            float S[8][4] = {};
            #pragma unroll
            for (int ni = 0; ni < 8; ni++) {
                unsigned bk[4][2];
                #pragma unroll
                for (int p = 0; p < 2; p++) {
                    int c  = ni * 8 + (lane & 7);
                    int sg = 4 * p + (lane >> 3);
                    uint32_t addr = kb + (uint32_t)(c * 128 + ((sg ^ (c & 7)) << 4));
                    ldsm4(bk[2 * p][0], bk[2 * p][1], bk[2 * p + 1][0], bk[2 * p + 1][1], addr);
                }
                #pragma unroll
                for (int ds = 0; ds < 4; ds++)
                    mma16816(S[ni], Qf[ds], bk[ds]);
            }

            const int rg0 = q0 + r0 + g, rg1 = rg0 + 8;
            if (k0 + 63 > q0 + r0) {
                #pragma unroll
                for (int ni = 0; ni < 8; ni++) {
                    int c0 = k0 + ni * 8 + 2 * t;
                    if (c0 > rg0)     S[ni][0] = -1e30f;
                    if (c0 + 1 > rg0) S[ni][1] = -1e30f;
                    if (c0 > rg1)     S[ni][2] = -1e30f;
                    if (c0 + 1 > rg1) S[ni][3] = -1e30f;
                }
            }

            float mx0 = -1e30f, mx1 = -1e30f;
            #pragma unroll
            for (int ni = 0; ni < 8; ni++) {
                mx0 = fmaxf(mx0, fmaxf(S[ni][0], S[ni][1]));
                mx1 = fmaxf(mx1, fmaxf(S[ni][2], S[ni][3]));
            }
            mx0 = fmaxf(mx0, __shfl_xor_sync(0xffffffffu, mx0, 1));
            mx0 = fmaxf(mx0, __shfl_xor_sync(0xffffffffu, mx0, 2));
            mx1 = fmaxf(mx1, __shfl_xor_sync(0xffffffffu, mx1, 1));
            mx1 = fmaxf(mx1, __shfl_xor_sync(0xffffffffu, mx1, 2));

            float mn0 = fmaxf(mrow[0], mx0), mn1 = fmaxf(mrow[1], mx1);
            float a0 = __expf(mrow[0] - mn0), a1 = __expf(mrow[1] - mn1);
            mrow[0] = mn0; mrow[1] = mn1;

            float s0 = 0.f, s1 = 0.f;
            #pragma unroll
            for (int ni = 0; ni < 8; ni++) {
                S[ni][0] = __expf(S[ni][0] - mn0);
                S[ni][1] = __expf(S[ni][1] - mn0);
                S[ni][2] = __expf(S[ni][2] - mn1);
                S[ni][3] = __expf(S[ni][3] - mn1);
                s0 += S[ni][0] + S[ni][1];
                s1 += S[ni][2] + S[ni][3];
            }
            s0 += __shfl_xor_sync(0xffffffffu, s0, 1);
            s0 += __shfl_xor_sync(0xffffffffu, s0, 2);
            s1 += __shfl_xor_sync(0xffffffffu, s1, 1);
            s1 += __shfl_xor_sync(0xffffffffu, s1, 2);
            lrow[0] = lrow[0] * a0 + s0;
            lrow[1] = lrow[1] * a1 + s1;

            #pragma unroll
            for (int di = 0; di < 8; di++) {
                O[di][0] *= a0; O[di][1] *= a0;
                O[di][2] *= a1; O[di][3] *= a1;
            }

            #pragma unroll
            for (int cs = 0; cs < 4; cs++) {
                unsigned ap[4];
                ap[0] = f2h2(S[2 * cs][0],     S[2 * cs][1]);
                ap[1] = f2h2(S[2 * cs][2],     S[2 * cs][3]);
                ap[2] = f2h2(S[2 * cs + 1][0], S[2 * cs + 1][1]);
                ap[3] = f2h2(S[2 * cs + 1][2], S[2 * cs + 1][3]);
                #pragma unroll
                for (int dp = 0; dp < 4; dp++) {
                    int row = cs * 16 + ((lane >> 3) & 1) * 8 + (lane & 7);
                    int sg  = 2 * dp + (lane >> 4);
                    uint32_t addr = vb + (uint32_t)(row * 128 + ((sg ^ (row & 7)) << 4));
                    unsigned bv[4];
                    ldsm4t(bv[0], bv[1], bv[2], bv[3], addr);
                    mma16816(O[2 * dp],     ap, bv);
                    mma16816(O[2 * dp + 1], ap, bv + 2);
                }
            }
        }
    }

    float inv0 = 1.f / lrow[0], inv1 = 1.f / lrow[1];
    int rg0 = q0 + r0 + g, rg1 = rg0 + 8;
    #pragma unroll
    for (int di = 0; di < 8; di++) {
        int c = h * DDIM + di * 8 + 2 * t;
        *(__half2*)(y + ((size_t)b * TDIM + rg0) * CDIM + c) =
            __floats2half2_rn(O[di][0] * inv0, O[di][1] * inv0);
        *(__half2*)(y + ((size_t)b * TDIM + rg1) * CDIM + c) =
            __floats2half2_rn(O[di][2] * inv1, O[di][3] * inv1);
    }
}

// ---------------------------------------------------------------------------
extern "C" void kernel_launch(void* const* d_in, const int* in_sizes, int n_in,
                              void* d_out, int out_size)
{
    const float* x     = (const float*)d_in[0];
    const float* Wqkv  = (const float*)d_in[1];
    const float* bqkv  = (const float*)d_in[2];
    const float* Wproj = (const float*)d_in[3];
    const float* bproj = (const float*)d_in[4];
    float* out = (float*)d_out;

    __half *xh, *wqkv, *wproj, *qkv, *yb;
    cudaGetSymbolAddress((void**)&xh, g_xh);
    cudaGetSymbolAddress((void**)&wqkv, g_wqkv);
    cudaGetSymbolAddress((void**)&wproj, g_wproj);
    cudaGetSymbolAddress((void**)&qkv, g_qkv);
    cudaGetSymbolAddress((void**)&yb, g_y);

    // 0) fused fp32 -> fp16 conversions (one launch)
    {
        int ntot = N_X + N_WQ + N_WP;
        f2h_all<<<(ntot / 4 + 255) / 256, 256>>>(x, Wqkv, Wproj, xh, wqkv, wproj);
    }

    cudaFuncSetAttribute(gemm_h<__half, 1>, cudaFuncAttributeMaxDynamicSharedMemorySize, GS_BYTES);
    cudaFuncSetAttribute(gemm_h<float, 0>,  cudaFuncAttributeMaxDynamicSharedMemorySize, GS_BYTES);

    // 1) QKV projection -> fp16 (Q cols scaled by 0.125)
    gemm_h<__half, 1><<<dim3(C3 / 128, MROWS / 128), 256, GS_BYTES>>>(
        xh, wqkv, bqkv, qkv, MROWS, C3, CDIM);

    // 2) Causal flash attention
    size_t fsm = 6 * FTILE;
    cudaFuncSetAttribute(flash_f16, cudaFuncAttributeMaxDynamicSharedMemorySize, (int)fsm);
    flash_f16<<<dim3(TDIM / 128, HDIM, BDIM), 256, fsm>>>(qkv, yb);

    // 3) Output projection -> fp32
    gemm_h<float, 0><<<dim3(CDIM / 128, MROWS / 128), 256, GS_BYTES>>>(
        yb, wproj, bproj, out, MROWS, CDIM, CDIM);
}